// round 15
// baseline (speedup 1.0000x reference)
#include <cuda_runtime.h>
#include <math.h>

#define Hh 2048
#define Wd 2048
#define MASKM 2047
#define Kk 16
#define Pp 15
#define TSTRIDE 144   // gather halo tile row stride
#define NBLK 512      // fused grid size (all co-resident: 4/SM x 148)

// scratch (static device globals — no allocation)
__device__ float g_win[Hh * Wd];
__device__ float g_C;
__device__ int   g_nf;
__device__ int   g_dfast[Kk];
__device__ float g_wfast[Kk];   // premultiplied by 1/3375
__device__ int   g_ng;
__device__ int   g_gsy[Kk], g_gsx[Kk];
__device__ float g_gw[Kk];
__device__ unsigned int g_tick;  // monotonic barrier ticket (never reset)

// ---------------------------------------------------------------------------
// Fused kernel: phase A = box-sum (+prep on block 0), device-wide software
// barrier, phase B = shifted gather (2 tiles/block).
// 512 blocks x 512 threads; smem = union(box rs 37.2KB, gather tile 27.6KB).
// All blocks co-resident (4/SM, 2048 thr/SM, regs<=32) -> barrier is safe.
// ---------------------------------------------------------------------------
__global__ void __launch_bounds__(512, 4)
k_fused(const float* __restrict__ img,
        const float* __restrict__ patterns,
        const float* __restrict__ vectors,
        float* __restrict__ out) {
    __shared__ float sh[143 * 65];   // box rs; reused as gather tile (6912)
    __shared__ int   sd[Kk];
    __shared__ float sw[Kk];
    __shared__ int   sng, snf;
    __shared__ float sC;

    int t = threadIdx.x;
    int b = blockIdx.x;

    // ================= phase A: prep (block 0) =================
    if (b == 0) {
        __shared__ float red[512];
        __shared__ int shy[Kk], shx[Kk];
        __shared__ int srare, sfast;
        const float scale = 1.0f / 3375.0f;

        if (t == 0) { srare = 0; sfast = 0; }
        if (t < Kk) {
            float vy = __ldg(vectors + 2 * t);
            float vx = __ldg(vectors + 2 * t + 1);
            int ny = ((int)floorf(vy)) & MASKM; if (ny >= 1024) ny -= 2048;
            int nx = ((int)floorf(vx)) & MASKM; if (nx >= 1024) nx -= 2048;
            shy[t] = ny; shx[t] = nx;
        }
        float s = 0.f;
        for (int i = t; i < 900; i += 512) {
            float4 f = __ldg((const float4*)patterns + i);
            s += f.x + f.y + f.z + f.w;
        }
        red[t] = s;
        __syncthreads();
        for (int off = 256; off > 0; off >>= 1) {
            if (t < off) red[t] += red[t + off];
            __syncthreads();
        }
        if (t < Kk) { g_dfast[t] = 0; g_wfast[t] = 0.f; }
        __syncthreads();
        if (t < Kk) {
            int ny = shy[t], nx = shx[t];
            int cnt = 0, first = Kk;
            #pragma unroll
            for (int m = 0; m < Kk; m++) {
                bool eq = (shy[m] == ny) && (shx[m] == nx);
                cnt += eq ? 1 : 0;
                if (eq && m < first) first = m;
            }
            bool isfirst = (first == t);
            bool inr = (ny >= -8 && ny <= 8 && nx >= -8 && nx <= 8);
            if (isfirst && inr) {
                int idx = atomicAdd(&sfast, 1);
                g_dfast[idx] = -ny * TSTRIDE - nx;
                g_wfast[idx] = (float)cnt * scale;
            }
            if (isfirst && !inr) {
                int idx = atomicAdd(&srare, 1);
                g_gsy[idx] = ny; g_gsx[idx] = nx;
                g_gw[idx] = (float)cnt * scale;
            }
        }
        __syncthreads();
        if (t == 0) {
            g_ng = srare;
            g_nf = sfast;
            g_C = ((float)Kk - red[0] / (float)(Pp * Pp)) / (float)(Kk - 1);
        }
        __syncthreads();
    }

    // ================= phase A: box tile (128 rows x 64 cols) =============
    {
        int j0 = (b & 31) * 64;
        int i0 = (b >> 5) * 128;

        // horizontal sliding sum, 16 outputs/thread
        for (int tt = t; tt < 143 * 4; tt += 512) {
            int r   = tt >> 2;
            int seg = tt & 3;
            int arow = i0 - 15 + r;
            int jb = j0 + seg * 16;
            float o[16];
            if (arow < 0) {
                #pragma unroll
                for (int c = 0; c < 16; c++) o[c] = 0.f;
            } else {
                const float* row = img + (size_t)arow * Wd;
                float v[32];
                if (jb >= 16) {
                    const float4* p = (const float4*)(row + jb - 16);
                    #pragma unroll
                    for (int q = 0; q < 8; q++) {
                        float4 f = __ldg(p + q);
                        v[4 * q + 0] = f.x; v[4 * q + 1] = f.y;
                        v[4 * q + 2] = f.z; v[4 * q + 3] = f.w;
                    }
                } else {
                    #pragma unroll
                    for (int x = 0; x < 32; x++) {
                        int c = jb - 16 + x;
                        v[x] = (c >= 0) ? __ldg(row + c) : 0.f;
                    }
                }
                float s = 0.f;
                #pragma unroll
                for (int x = 1; x <= 15; x++) s += v[x];
                o[0] = s;
                #pragma unroll
                for (int c = 1; c < 16; c++) { s += v[15 + c] - v[c]; o[c] = s; }
            }
            float* dst = sh + r * 65 + seg * 16;
            #pragma unroll
            for (int c = 0; c < 16; c++) dst[c] = o[c];
        }
        __syncthreads();

        // vertical sliding sum -> win
        int col = t & 63;
        int R0  = (t >> 6) * 16;
        const float* cp = sh + col;
        float s = 0.f;
        #pragma unroll
        for (int r = 0; r < 15; r++) s += cp[(R0 + r) * 65];
        float* outp = g_win + (size_t)(i0 + R0) * Wd + j0 + col;
        #pragma unroll
        for (int rr = 0; rr < 16; rr++) {
            outp[(size_t)rr * Wd] = s;
            if (rr < 15)
                s += cp[(R0 + rr + 15) * 65] - cp[(R0 + rr) * 65];
        }
        __syncthreads();   // everyone done with sh before barrier/reuse
    }

    // ================= device-wide barrier (replay-safe, monotonic) =======
    __threadfence();
    if (t == 0) {
        unsigned int old = atomicAdd(&g_tick, 1u);
        unsigned int target = (old / NBLK + 1u) * NBLK;
        volatile unsigned int* vp = &g_tick;
        while ((int)(*vp - target) < 0) { }
    }
    __syncthreads();
    __threadfence();

    // load gather params
    if (t < Kk) { sd[t] = g_dfast[t]; sw[t] = g_wfast[t]; }
    if (t == 0) { sng = g_ng; snf = g_nf; sC = g_C; }
    __syncthreads();

    // ================= phase B: gather, 2 tiles of 32x128 =================
    #define GATHER_LOOP(NM)                                        \
        _Pragma("unroll")                                          \
        for (int m = 0; m < (NM); m++) {                           \
            float w = sw[m];                                       \
            const float* p = base + sd[m];                         \
            _Pragma("unroll")                                      \
            for (int rr = 0; rr < 8; rr++)                         \
                acc[rr] += w * p[rr * TSTRIDE];                    \
        }

    int tx = t & 127;
    int R0 = (t >> 7) * 8;   // 0, 8, 16, 24

    #pragma unroll 1
    for (int half = 0; half < 2; half++) {
        int g  = 2 * b + half;           // gather tile id 0..1023
        int j0 = (g & 15) * 128;
        int i0 = (g >> 4) * 32;

        // stage 48 x 144 halo via float4
        for (int idx = t; idx < 48 * 36; idx += 512) {
            int u  = idx / 36;
            int vq = idx - u * 36;
            int gr = (i0 - 8 + u) & MASKM;
            int gc = (j0 - 8 + 4 * vq) & MASKM;
            float4 f = __ldg((const float4*)(g_win + (size_t)gr * Wd + gc));
            *(float4*)&sh[u * TSTRIDE + 4 * vq] = f;
        }
        __syncthreads();

        const float* base = sh + (R0 + 8) * TSTRIDE + tx + 8;

        float acc[8];
        #pragma unroll
        for (int rr = 0; rr < 8; rr++) acc[rr] = 0.f;

        int nf = snf;
        if (nf <= 8)       { GATHER_LOOP(8)  }
        else if (nf == 9)  { GATHER_LOOP(9)  }
        else if (nf == 10) { GATHER_LOOP(10) }
        else if (nf == 11) { GATHER_LOOP(11) }
        else if (nf == 12) { GATHER_LOOP(12) }
        else if (nf == 13) { GATHER_LOOP(13) }
        else if (nf == 14) { GATHER_LOOP(14) }
        else               { GATHER_LOOP(16) }

        int ng = sng;
        if (ng > 0) {
            for (int m = 0; m < ng; m++) {
                int sy = g_gsy[m], sx = g_gsx[m];
                float w = g_gw[m];
                int gc = (j0 + tx - sx) & MASKM;
                #pragma unroll 1
                for (int rr = 0; rr < 8; rr++) {
                    int gr = (i0 + R0 + rr - sy) & MASKM;
                    acc[rr] += w * __ldg(g_win + (size_t)gr * Wd + gc);
                }
            }
        }

        float c = sC;
        float* op = out + (size_t)(i0 + R0) * Wd + j0 + tx;
        #pragma unroll
        for (int rr = 0; rr < 8; rr++)
            op[(size_t)rr * Wd] = c + acc[rr];

        __syncthreads();   // protect sh before next tile staging
    }
    #undef GATHER_LOOP
}

// ---------------------------------------------------------------------------
extern "C" void kernel_launch(void* const* d_in, const int* in_sizes, int n_in,
                              void* d_out, int out_size) {
    const float* x        = (const float*)d_in[0];  // (1,1,2048,2048)
    const float* patterns = (const float*)d_in[1];  // (16,15,15)
    const float* vectors  = (const float*)d_in[2];  // (16,2)
    float* out = (float*)d_out;                     // (2048,2048)

    k_fused<<<NBLK, 512>>>(x, patterns, vectors, out);
}

// round 16
// speedup vs baseline: 1.2373x; 1.2373x over previous
#include <cuda_runtime.h>
#include <math.h>

#define Hh 2048
#define Wd 2048
#define MASKM 2047
#define Kk 16
#define Pp 15
#define TSTRIDE 144   // gather halo tile row stride

// scratch (static device globals — no allocation)
__device__ float g_win[Hh * Wd];
__device__ float g_C;
__device__ int   g_nf;          // number of live fast entries (<= 16)
__device__ int   g_dfast[Kk];   // smem-relative deltas (padded, w=0)
__device__ float g_wfast[Kk];   // weights premultiplied by 1/3375
__device__ int   g_ng;          // out-of-range shifts (never in practice)
__device__ int   g_gsy[Kk], g_gsx[Kk];
__device__ float g_gw[Kk];      // premultiplied by 1/3375

// ---------------------------------------------------------------------------
// Kernel 1: fused separable 15x15 box-sum (zero-padded above/left).
// win[i][j] = sum_{a=i-15..i-1, b=j-15..j-1} img[a][b]
// Tile: 128 rows x 64 cols per block; rowsum staged in SMEM (143 x 64,
// stride 65). grid = (32, 16), 512 threads. (R14-proven, unchanged except
// the PDL trigger at the end.)
// Block (0,0) additionally does ALL prep work with fully-parallel dedupe.
// ---------------------------------------------------------------------------
__global__ void __launch_bounds__(512)
k_box(const float* __restrict__ img,
      const float* __restrict__ patterns,
      const float* __restrict__ vectors) {
    __shared__ float rs[143 * 65];

    int t = threadIdx.x;
    int j0 = blockIdx.x * 64;
    int i0 = blockIdx.y * 128;

    // ---- prep (block (0,0) only) ----
    if (blockIdx.x == 0 && blockIdx.y == 0) {
        __shared__ float red[512];
        __shared__ int shy[Kk], shx[Kk];
        __shared__ int srare, sfast;
        const float scale = 1.0f / 3375.0f;

        if (t == 0) { srare = 0; sfast = 0; }
        if (t < Kk) {
            float vy = __ldg(vectors + 2 * t);
            float vx = __ldg(vectors + 2 * t + 1);
            int ny = ((int)floorf(vy)) & MASKM; if (ny >= 1024) ny -= 2048;
            int nx = ((int)floorf(vx)) & MASKM; if (nx >= 1024) nx -= 2048;
            shy[t] = ny; shx[t] = nx;
        }
        float s = 0.f;
        for (int i = t; i < 900; i += 512) {   // 3600 floats = 900 float4
            float4 f = __ldg((const float4*)patterns + i);
            s += f.x + f.y + f.z + f.w;
        }
        red[t] = s;
        __syncthreads();
        for (int off = 256; off > 0; off >>= 1) {
            if (t < off) red[t] += red[t + off];
            __syncthreads();
        }
        if (t < Kk) { g_dfast[t] = 0; g_wfast[t] = 0.f; }
        __syncthreads();
        if (t < Kk) {
            int ny = shy[t], nx = shx[t];
            int cnt = 0, first = Kk;
            #pragma unroll
            for (int m = 0; m < Kk; m++) {
                bool eq = (shy[m] == ny) && (shx[m] == nx);
                cnt += eq ? 1 : 0;
                if (eq && m < first) first = m;
            }
            bool isfirst = (first == t);
            bool inr = (ny >= -8 && ny <= 8 && nx >= -8 && nx <= 8);
            if (isfirst && inr) {
                int idx = atomicAdd(&sfast, 1);   // pack live entries first
                g_dfast[idx] = -ny * TSTRIDE - nx;
                g_wfast[idx] = (float)cnt * scale;
            }
            if (isfirst && !inr) {
                int idx = atomicAdd(&srare, 1);
                g_gsy[idx] = ny; g_gsx[idx] = nx;
                g_gw[idx] = (float)cnt * scale;
            }
        }
        __syncthreads();
        if (t == 0) {
            g_ng = srare;
            g_nf = sfast;
            g_C = ((float)Kk - red[0] / (float)(Pp * Pp)) / (float)(Kk - 1);
        }
        __syncthreads();
    }

    // ---- phase 1: horizontal sliding sum, 16 outputs/thread ----
    for (int tt = t; tt < 143 * 4; tt += 512) {
        int r   = tt >> 2;
        int seg = tt & 3;
        int arow = i0 - 15 + r;
        int jb = j0 + seg * 16;
        float o[16];
        if (arow < 0) {
            #pragma unroll
            for (int c = 0; c < 16; c++) o[c] = 0.f;
        } else {
            const float* row = img + (size_t)arow * Wd;
            float v[32];
            if (jb >= 16) {
                const float4* p = (const float4*)(row + jb - 16);
                #pragma unroll
                for (int q = 0; q < 8; q++) {
                    float4 f = __ldg(p + q);
                    v[4 * q + 0] = f.x; v[4 * q + 1] = f.y;
                    v[4 * q + 2] = f.z; v[4 * q + 3] = f.w;
                }
            } else {
                #pragma unroll
                for (int x = 0; x < 32; x++) {
                    int c = jb - 16 + x;
                    v[x] = (c >= 0) ? __ldg(row + c) : 0.f;
                }
            }
            float s = 0.f;
            #pragma unroll
            for (int x = 1; x <= 15; x++) s += v[x];
            o[0] = s;
            #pragma unroll
            for (int c = 1; c < 16; c++) { s += v[15 + c] - v[c]; o[c] = s; }
        }
        float* dst = rs + r * 65 + seg * 16;
        #pragma unroll
        for (int c = 0; c < 16; c++) dst[c] = o[c];
    }
    __syncthreads();

    // ---- phase 2: vertical sliding sum -> win ----
    int col = t & 63;
    int R0  = (t >> 6) * 16;
    const float* cp = rs + col;
    float s = 0.f;
    #pragma unroll
    for (int r = 0; r < 15; r++) s += cp[(R0 + r) * 65];
    float* outp = g_win + (size_t)(i0 + R0) * Wd + j0 + col;
    #pragma unroll
    for (int rr = 0; rr < 16; rr++) {
        outp[(size_t)rr * Wd] = s;
        if (rr < 15)
            s += cp[(R0 + rr + 15) * 65] - cp[(R0 + rr) * 65];
    }

    // PDL: allow the dependent gather grid to begin launching.
    cudaTriggerProgrammaticLaunchCompletion();
}

// ---------------------------------------------------------------------------
// Kernel 2: out[i,j] = C + sum_m w'_m * win[(i-sy)&M][(j-sx)&M]
// 32x128 tile/block, 512 threads (__launch_bounds__(512,4): 2048 thr/SM,
// regs=32 — R14-proven shape). 48x144 halo in SMEM (27.6KB).
// nf-exact ladder (8..14/16). Launched with PDL: waits on
// cudaGridDependencySynchronize() before reading box outputs.
// grid = (16, 64); thread = 1 col x 8 rows (4 row-groups).
// ---------------------------------------------------------------------------
#define GATHER_LOOP(NM)                                        \
    _Pragma("unroll")                                          \
    for (int m = 0; m < (NM); m++) {                           \
        float w = sw[m];                                       \
        const float* p = base + sd[m];                         \
        _Pragma("unroll")                                      \
        for (int rr = 0; rr < 8; rr++)                         \
            acc[rr] += w * p[rr * TSTRIDE];                    \
    }

__global__ void __launch_bounds__(512, 4) k_gather(float* __restrict__ out) {
    __shared__ float tile[48 * TSTRIDE];
    __shared__ int   sd[Kk];
    __shared__ float sw[Kk];
    __shared__ int   sng, snf;
    __shared__ float sC;

    // PDL: wait until k_box's memory (g_win + prep lists) is visible.
    cudaGridDependencySynchronize();

    int t = threadIdx.x;
    int j0 = blockIdx.x * 128;
    int i0 = blockIdx.y * 32;

    if (t < Kk) { sd[t] = g_dfast[t]; sw[t] = g_wfast[t]; }
    if (t == 0) { sng = g_ng; snf = g_nf; sC = g_C; }

    // stage 48 x 144 halo via float4 (j0-8 ≡ 0 mod 4; wrap never splits)
    for (int idx = t; idx < 48 * 36; idx += 512) {
        int u  = idx / 36;
        int vq = idx - u * 36;
        int gr = (i0 - 8 + u) & MASKM;
        int gc = (j0 - 8 + 4 * vq) & MASKM;
        float4 f = __ldg((const float4*)(g_win + (size_t)gr * Wd + gc));
        *(float4*)&tile[u * TSTRIDE + 4 * vq] = f;
    }
    __syncthreads();

    int tx = t & 127;
    int R0 = (t >> 7) * 8;   // 0, 8, 16, 24
    const float* base = tile + (R0 + 8) * TSTRIDE + tx + 8;

    float acc[8];
    #pragma unroll
    for (int rr = 0; rr < 8; rr++) acc[rr] = 0.f;

    int nf = snf;
    if (nf <= 8)       { GATHER_LOOP(8)  }
    else if (nf == 9)  { GATHER_LOOP(9)  }
    else if (nf == 10) { GATHER_LOOP(10) }
    else if (nf == 11) { GATHER_LOOP(11) }
    else if (nf == 12) { GATHER_LOOP(12) }
    else if (nf == 13) { GATHER_LOOP(13) }
    else if (nf == 14) { GATHER_LOOP(14) }
    else               { GATHER_LOOP(16) }

    int ng = sng;
    if (ng > 0) {  // uniform, essentially never taken
        for (int m = 0; m < ng; m++) {
            int sy = g_gsy[m], sx = g_gsx[m];
            float w = g_gw[m];
            int gc = (j0 + tx - sx) & MASKM;
            #pragma unroll 1
            for (int rr = 0; rr < 8; rr++) {
                int gr = (i0 + R0 + rr - sy) & MASKM;
                acc[rr] += w * __ldg(g_win + (size_t)gr * Wd + gc);
            }
        }
    }

    float c = sC;
    float* op = out + (size_t)(i0 + R0) * Wd + j0 + tx;
    #pragma unroll
    for (int rr = 0; rr < 8; rr++)
        op[(size_t)rr * Wd] = c + acc[rr];
}

// ---------------------------------------------------------------------------
extern "C" void kernel_launch(void* const* d_in, const int* in_sizes, int n_in,
                              void* d_out, int out_size) {
    const float* x        = (const float*)d_in[0];  // (1,1,2048,2048)
    const float* patterns = (const float*)d_in[1];  // (16,15,15)
    const float* vectors  = (const float*)d_in[2];  // (16,2)
    float* out = (float*)d_out;                     // (2048,2048)

    k_box<<<dim3(32, 16), 512>>>(x, patterns, vectors);

    // Dependent launch: overlap gather's launch/init with box's tail.
    cudaLaunchAttribute attrs[1];
    attrs[0].id = cudaLaunchAttributeProgrammaticStreamSerialization;
    attrs[0].val.programmaticStreamSerializationAllowed = 1;

    cudaLaunchConfig_t cfg = {};
    cfg.gridDim = dim3(16, 64);
    cfg.blockDim = dim3(512);
    cfg.dynamicSmemBytes = 0;
    cfg.stream = 0;
    cfg.attrs = attrs;
    cfg.numAttrs = 1;

    cudaLaunchKernelEx(&cfg, k_gather, out);
}

// round 17
// speedup vs baseline: 1.3232x; 1.0694x over previous
#include <cuda_runtime.h>
#include <math.h>

#define Hh 2048
#define Wd 2048
#define MASKM 2047
#define Kk 16
#define Pp 15
#define TSTRIDE 144   // gather halo tile row stride
#define RSTR 68       // box rowsum smem stride (16B-aligned rows)

// scratch (static device globals — no allocation)
__device__ float g_win[Hh * Wd];
__device__ float g_C;
__device__ int   g_nf;          // number of live fast entries (<= 16)
__device__ int   g_dfast[Kk];   // smem-relative deltas (padded, w=0)
__device__ float g_wfast[Kk];   // weights premultiplied by 1/3375
__device__ int   g_ng;          // out-of-range shifts (never in practice)
__device__ int   g_gsy[Kk], g_gsx[Kk];
__device__ float g_gw[Kk];      // premultiplied by 1/3375

// ---------------------------------------------------------------------------
// Kernel 1: fused separable 15x15 box-sum (zero-padded above/left).
// win[i][j] = sum_{a=i-15..i-1, b=j-15..j-1} img[a][b]
// Tile: 128 rows x 64 cols per block; rowsum staged in SMEM (143 x 64,
// stride 68 -> aligned STS.128 stores). grid = (32, 16), 256 threads,
// 8 outputs/thread in phase 1 (R6-proven, no register spills).
// Block (0,0) additionally does ALL prep work with fully-parallel dedupe.
// ---------------------------------------------------------------------------
__global__ void __launch_bounds__(256)
k_box(const float* __restrict__ img,
      const float* __restrict__ patterns,
      const float* __restrict__ vectors) {
    __shared__ float rs[143 * RSTR];

    int t = threadIdx.x;
    int j0 = blockIdx.x * 64;
    int i0 = blockIdx.y * 128;

    // ---- prep (block (0,0) only) ----
    if (blockIdx.x == 0 && blockIdx.y == 0) {
        __shared__ float red[256];
        __shared__ int shy[Kk], shx[Kk];
        __shared__ int srare, sfast;
        const float scale = 1.0f / 3375.0f;

        if (t == 0) { srare = 0; sfast = 0; }
        if (t < Kk) {
            float vy = __ldg(vectors + 2 * t);
            float vx = __ldg(vectors + 2 * t + 1);
            int ny = ((int)floorf(vy)) & MASKM; if (ny >= 1024) ny -= 2048;
            int nx = ((int)floorf(vx)) & MASKM; if (nx >= 1024) nx -= 2048;
            shy[t] = ny; shx[t] = nx;
        }
        float s = 0.f;
        for (int i = t; i < 900; i += 256) {   // 3600 floats = 900 float4
            float4 f = __ldg((const float4*)patterns + i);
            s += f.x + f.y + f.z + f.w;
        }
        red[t] = s;
        __syncthreads();
        for (int off = 128; off > 0; off >>= 1) {
            if (t < off) red[t] += red[t + off];
            __syncthreads();
        }
        if (t < Kk) { g_dfast[t] = 0; g_wfast[t] = 0.f; }
        __syncthreads();
        if (t < Kk) {
            int ny = shy[t], nx = shx[t];
            int cnt = 0, first = Kk;
            #pragma unroll
            for (int m = 0; m < Kk; m++) {
                bool eq = (shy[m] == ny) && (shx[m] == nx);
                cnt += eq ? 1 : 0;
                if (eq && m < first) first = m;
            }
            bool isfirst = (first == t);
            bool inr = (ny >= -8 && ny <= 8 && nx >= -8 && nx <= 8);
            if (isfirst && inr) {
                int idx = atomicAdd(&sfast, 1);   // pack live entries first
                g_dfast[idx] = -ny * TSTRIDE - nx;
                g_wfast[idx] = (float)cnt * scale;
            }
            if (isfirst && !inr) {
                int idx = atomicAdd(&srare, 1);
                g_gsy[idx] = ny; g_gsx[idx] = nx;
                g_gw[idx] = (float)cnt * scale;
            }
        }
        __syncthreads();
        if (t == 0) {
            g_ng = srare;
            g_nf = sfast;
            g_C = ((float)Kk - red[0] / (float)(Pp * Pp)) / (float)(Kk - 1);
        }
        __syncthreads();
    }

    // ---- phase 1: horizontal sliding sum, 8 outputs/thread ----
    // 1144 tasks = 143 rows x 8 segments of 8 cols; 256 threads.
    for (int tt = t; tt < 143 * 8; tt += 256) {
        int r   = tt >> 3;
        int seg = tt & 7;
        int arow = i0 - 15 + r;
        int jb = j0 + seg * 8;
        float o[8];
        if (arow < 0) {
            #pragma unroll
            for (int c = 0; c < 8; c++) o[c] = 0.f;
        } else {
            const float* row = img + (size_t)arow * Wd;
            float v[24];
            if (jb >= 16) {
                const float4* p = (const float4*)(row + jb - 16);
                #pragma unroll
                for (int q = 0; q < 6; q++) {
                    float4 f = __ldg(p + q);
                    v[4 * q + 0] = f.x; v[4 * q + 1] = f.y;
                    v[4 * q + 2] = f.z; v[4 * q + 3] = f.w;
                }
            } else {
                #pragma unroll
                for (int x = 0; x < 24; x++) {
                    int c = jb - 16 + x;
                    v[x] = (c >= 0) ? __ldg(row + c) : 0.f;
                }
            }
            float s = 0.f;
            #pragma unroll
            for (int x = 1; x <= 15; x++) s += v[x];
            o[0] = s;
            #pragma unroll
            for (int c = 1; c < 8; c++) { s += v[15 + c] - v[c]; o[c] = s; }
        }
        // aligned float4 stores (RSTR and seg*8 are multiples of 4)
        float4* dst = (float4*)(rs + r * RSTR + seg * 8);
        dst[0] = make_float4(o[0], o[1], o[2], o[3]);
        dst[1] = make_float4(o[4], o[5], o[6], o[7]);
    }
    __syncthreads();

    // ---- phase 2: vertical sliding sum -> win (R6-proven 32-row chains) ----
    int col = t & 63;
    int R0  = (t >> 6) * 32;
    const float* cp = rs + col;
    float s = 0.f;
    #pragma unroll
    for (int r = 0; r < 15; r++) s += cp[(R0 + r) * RSTR];
    float* outp = g_win + (size_t)(i0 + R0) * Wd + j0 + col;
    #pragma unroll
    for (int rr = 0; rr < 32; rr++) {
        outp[(size_t)rr * Wd] = s;
        if (rr < 31)
            s += cp[(R0 + rr + 15) * RSTR] - cp[(R0 + rr) * RSTR];
    }

    // PDL: allow the dependent gather grid to begin launching.
    cudaTriggerProgrammaticLaunchCompletion();
}

// ---------------------------------------------------------------------------
// Kernel 2: out[i,j] = C + sum_m w'_m * win[(i-sy)&M][(j-sx)&M]
// 32x128 tile/block, 512 threads (__launch_bounds__(512,4): 2048 thr/SM,
// regs=32 — R14-proven shape, byte-identical). 48x144 halo in SMEM.
// nf-exact ladder (8..14/16). PDL-gated on k_box completion.
// grid = (16, 64); thread = 1 col x 8 rows (4 row-groups).
// ---------------------------------------------------------------------------
#define GATHER_LOOP(NM)                                        \
    _Pragma("unroll")                                          \
    for (int m = 0; m < (NM); m++) {                           \
        float w = sw[m];                                       \
        const float* p = base + sd[m];                         \
        _Pragma("unroll")                                      \
        for (int rr = 0; rr < 8; rr++)                         \
            acc[rr] += w * p[rr * TSTRIDE];                    \
    }

__global__ void __launch_bounds__(512, 4) k_gather(float* __restrict__ out) {
    __shared__ float tile[48 * TSTRIDE];
    __shared__ int   sd[Kk];
    __shared__ float sw[Kk];
    __shared__ int   sng, snf;
    __shared__ float sC;

    // PDL: wait until k_box's memory (g_win + prep lists) is visible.
    cudaGridDependencySynchronize();

    int t = threadIdx.x;
    int j0 = blockIdx.x * 128;
    int i0 = blockIdx.y * 32;

    if (t < Kk) { sd[t] = g_dfast[t]; sw[t] = g_wfast[t]; }
    if (t == 0) { sng = g_ng; snf = g_nf; sC = g_C; }

    // stage 48 x 144 halo via float4 (j0-8 ≡ 0 mod 4; wrap never splits)
    for (int idx = t; idx < 48 * 36; idx += 512) {
        int u  = idx / 36;
        int vq = idx - u * 36;
        int gr = (i0 - 8 + u) & MASKM;
        int gc = (j0 - 8 + 4 * vq) & MASKM;
        float4 f = __ldg((const float4*)(g_win + (size_t)gr * Wd + gc));
        *(float4*)&tile[u * TSTRIDE + 4 * vq] = f;
    }
    __syncthreads();

    int tx = t & 127;
    int R0 = (t >> 7) * 8;   // 0, 8, 16, 24
    const float* base = tile + (R0 + 8) * TSTRIDE + tx + 8;

    float acc[8];
    #pragma unroll
    for (int rr = 0; rr < 8; rr++) acc[rr] = 0.f;

    int nf = snf;
    if (nf <= 8)       { GATHER_LOOP(8)  }
    else if (nf == 9)  { GATHER_LOOP(9)  }
    else if (nf == 10) { GATHER_LOOP(10) }
    else if (nf == 11) { GATHER_LOOP(11) }
    else if (nf == 12) { GATHER_LOOP(12) }
    else if (nf == 13) { GATHER_LOOP(13) }
    else if (nf == 14) { GATHER_LOOP(14) }
    else               { GATHER_LOOP(16) }

    int ng = sng;
    if (ng > 0) {  // uniform, essentially never taken
        for (int m = 0; m < ng; m++) {
            int sy = g_gsy[m], sx = g_gsx[m];
            float w = g_gw[m];
            int gc = (j0 + tx - sx) & MASKM;
            #pragma unroll 1
            for (int rr = 0; rr < 8; rr++) {
                int gr = (i0 + R0 + rr - sy) & MASKM;
                acc[rr] += w * __ldg(g_win + (size_t)gr * Wd + gc);
            }
        }
    }

    float c = sC;
    float* op = out + (size_t)(i0 + R0) * Wd + j0 + tx;
    #pragma unroll
    for (int rr = 0; rr < 8; rr++)
        op[(size_t)rr * Wd] = c + acc[rr];
}

// ---------------------------------------------------------------------------
extern "C" void kernel_launch(void* const* d_in, const int* in_sizes, int n_in,
                              void* d_out, int out_size) {
    const float* x        = (const float*)d_in[0];  // (1,1,2048,2048)
    const float* patterns = (const float*)d_in[1];  // (16,15,15)
    const float* vectors  = (const float*)d_in[2];  // (16,2)
    float* out = (float*)d_out;                     // (2048,2048)

    k_box<<<dim3(32, 16), 256>>>(x, patterns, vectors);

    // Dependent launch: overlap gather's launch/init with box's tail.
    cudaLaunchAttribute attrs[1];
    attrs[0].id = cudaLaunchAttributeProgrammaticStreamSerialization;
    attrs[0].val.programmaticStreamSerializationAllowed = 1;

    cudaLaunchConfig_t cfg = {};
    cfg.gridDim = dim3(16, 64);
    cfg.blockDim = dim3(512);
    cfg.dynamicSmemBytes = 0;
    cfg.stream = 0;
    cfg.attrs = attrs;
    cfg.numAttrs = 1;

    cudaLaunchKernelEx(&cfg, k_gather, out);
}